// round 9
// baseline (speedup 1.0000x reference)
#include <cuda_runtime.h>
#include <cuda_fp16.h>
#include <cooperative_groups.h>
#include <cstdint>

namespace cg = cooperative_groups;

#define NNODES 50000
#define NREL   8
#define D      128
#define NSEG   (NREL * NNODES)      // 400000
#define MAXE   1700000
#define ROWS   128                  // output rows per block
#define NTHR   512

// -------- scratch (device globals; no allocation allowed) --------
__device__ int    g_deg[NSEG];
__device__ int    g_off[NSEG + 1];
__device__ int    g_cur[NSEG];
__device__ int    g_bsum[512];
__device__ int    g_sorted[MAXE];
__device__ int    g_st_ei;           // words/elem of edge_index (1=int32, 2=int64)
__device__ int    g_st_et;
__device__ __half g_wh[(NREL + 1) * D * D];   // fp16 [W_0..W_7, root], [out][in]
__device__ __half g_xh[(size_t)NNODES * D];   // fp16 copy of x

// -------- merged setup: detect dtype + cvt W/x to fp16 + zero deg --------
__global__ void k_prep(const float* __restrict__ W, const float* __restrict__ root,
                       const float* __restrict__ x, int n,
                       const int* __restrict__ ei_w, const int* __restrict__ et_w) {
    int i = blockIdx.x * blockDim.x + threadIdx.x;
    int stride = gridDim.x * blockDim.x;
    if (i == 0) {
        bool e64 = true, t64 = true;
        #pragma unroll
        for (int j = 1; j < 64; j += 2) {
            e64 = e64 && (ei_w[j] == 0);
            t64 = t64 && (et_w[j] == 0);
        }
        g_st_ei = e64 ? 2 : 1;
        g_st_et = t64 ? 2 : 1;
    }
    for (int j = i; j < NSEG; j += stride) g_deg[j] = 0;
    const int nw = NREL * D * D;
    for (int j = i; j < nw + D * D; j += stride)
        g_wh[j] = __float2half(j < nw ? W[j] : root[j - nw]);
    int nx4 = n * D / 4;
    for (int j = i; j < nx4; j += stride) {
        float4 v = __ldg((const float4*)x + j);
        __half2* o = (__half2*)(g_xh + (size_t)j * 4);
        o[0] = __floats2half2_rn(v.x, v.y);
        o[1] = __floats2half2_rn(v.z, v.w);
    }
}

__global__ void k_hist(const int* __restrict__ ei_w, const int* __restrict__ et_w, int E) {
    int i = blockIdx.x * blockDim.x + threadIdx.x;
    if (i < E) {
        int st = g_st_ei, stt = g_st_et;
        int s = ei_w[(size_t)i * st];
        int t = et_w[(size_t)i * stt];
        int key = t * NNODES + s;
        if ((unsigned)key < NSEG) atomicAdd(&g_deg[key], 1);
    }
}

// -------- cooperative scan + scatter (replaces scan1/scan2/scan3/scatter) --------
__global__ void __launch_bounds__(1024)
k_css(const int* __restrict__ ei_w, const int* __restrict__ et_w, int E) {
    __shared__ int sh[1024];
    int tid = threadIdx.x, b = blockIdx.x, nb = gridDim.x;
    int chunk = (NSEG + nb - 1) / nb;
    int lo = b * chunk;
    int hi = min(lo + chunk, NSEG);
    int carry = 0;

    // phase A: per-block local exclusive scan of its chunk
    for (int t0 = lo; t0 < hi; t0 += 1024) {
        int i = t0 + tid;
        int v = (i < hi) ? g_deg[i] : 0;
        sh[tid] = v;
        __syncthreads();
        #pragma unroll
        for (int off = 1; off < 1024; off <<= 1) {
            int t = (tid >= off) ? sh[tid - off] : 0;
            __syncthreads();
            sh[tid] += t;
            __syncthreads();
        }
        if (i < hi) g_off[i] = sh[tid] - v + carry;
        int tot = sh[1023];
        __syncthreads();
        carry += tot;
    }
    if (tid == 0) g_bsum[b] = carry;
    cg::this_grid().sync();

    // phase B: every block computes its base from block sums, applies it
    int v2 = (tid < nb) ? g_bsum[tid] : 0;
    sh[tid] = v2;
    __syncthreads();
    #pragma unroll
    for (int off = 1; off < 1024; off <<= 1) {
        int t = (tid >= off) ? sh[tid - off] : 0;
        __syncthreads();
        sh[tid] += t;
        __syncthreads();
    }
    int base = sh[b] - g_bsum[b];     // exclusive prefix for this block
    __syncthreads();
    for (int t0 = lo; t0 < hi; t0 += 1024) {
        int i = t0 + tid;
        if (i < hi) {
            int o = g_off[i] + base;
            g_off[i] = o;
            g_cur[i] = o;
        }
    }
    if (b == 0 && tid == 0) g_off[NSEG] = E;
    cg::this_grid().sync();

    // phase C: scatter
    int st = g_st_ei, stt = g_st_et;
    for (int i = b * 1024 + tid; i < E; i += nb * 1024) {
        int s = ei_w[(size_t)i * st];
        int d = ei_w[((size_t)E + i) * st];
        int t = et_w[(size_t)i * stt];
        int key = t * NNODES + s;
        if ((unsigned)key < NSEG) {
            int pos = atomicAdd(&g_cur[key], 1);
            if ((unsigned)pos < MAXE) g_sorted[pos] = d;
        }
    }
}

// -------- fused gather-mean + fp16 MMA GEMM (software pipelined) --------
__device__ __forceinline__ void mma_f16(float* c,
                                        unsigned a0, unsigned a1, unsigned a2, unsigned a3,
                                        unsigned b0, unsigned b1) {
    asm volatile(
        "mma.sync.aligned.m16n8k16.row.col.f32.f16.f16.f32 "
        "{%0,%1,%2,%3},{%4,%5,%6,%7},{%8,%9},{%0,%1,%2,%3};"
        : "+f"(c[0]), "+f"(c[1]), "+f"(c[2]), "+f"(c[3])
        : "r"(a0), "r"(a1), "r"(a2), "r"(a3), "r"(b0), "r"(b1));
}

__device__ __forceinline__ void acc_h8(float* a, uint4 u) {
    float2 f0 = __half22float2(*(__half2*)&u.x);
    float2 f1 = __half22float2(*(__half2*)&u.y);
    float2 f2 = __half22float2(*(__half2*)&u.z);
    float2 f3 = __half22float2(*(__half2*)&u.w);
    a[0] += f0.x; a[1] += f0.y; a[2] += f1.x; a[3] += f1.y;
    a[4] += f2.x; a[5] += f2.y; a[6] += f3.x; a[7] += f3.y;
}

__device__ __forceinline__ void cp16(uint32_t sdst, const void* gsrc) {
    asm volatile("cp.async.cg.shared.global [%0], [%1], 16;" :: "r"(sdst), "l"(gsrc));
}

#define FUSED_SMEM (2 * 128 * 136 * 2)   // As + Bs, 69632 B

__global__ void __launch_bounds__(NTHR)
k_fused(const float* __restrict__ bias, float* __restrict__ out, int n) {
    extern __shared__ __half smh[];
    __half (*As)[136] = (__half(*)[136])smh;
    __half (*Bs)[136] = (__half(*)[136])(smh + 128 * 136);

    int tid  = threadIdx.x;
    int lane = tid & 31;
    int warp = tid >> 5;                 // 0..15
    int hw   = lane >> 4;
    int hl   = lane & 15;
    unsigned hmask = 0xFFFFu << (hw * 16);
    int rsub = warp * 2 + hw;            // 0..31
    int rowBase = blockIdx.x * ROWS;
    int gpr = lane >> 2;
    int tg  = lane & 3;
    int rowStrip = (warp & 7) * 16;
    int colBase  = (warp >> 3) * 64;

    float acc[8][4];
    #pragma unroll
    for (int t = 0; t < 8; t++)
        #pragma unroll
        for (int q = 0; q < 4; q++) acc[t][q] = 0.f;

    uint4 ag[4];   // gathered A rows for the NEXT slab (register-held)

    // prologue: slab "root" (simple x copy)
    #pragma unroll
    for (int p = 0; p < 4; p++) {
        int node = rowBase + p * 32 + rsub;
        ag[p] = (node < n) ? __ldg((const uint4*)(g_xh + (size_t)node * D) + hl)
                           : make_uint4(0u, 0u, 0u, 0u);
    }

    // slab order: it=0 -> root (s=8), it=1..8 -> relations 0..7
    #pragma unroll 1
    for (int it = 0; it < 9; it++) {
        int s = (it == 0) ? NREL : (it - 1);
        __syncthreads();                 // previous MMA done reading As/Bs

        // commit register-held A rows
        #pragma unroll
        for (int p = 0; p < 4; p++)
            *(uint4*)&As[p * 32 + rsub][hl * 8] = ag[p];

        // stage B tile via cp.async
        const __half* Bg = g_wh + (s << 14);
        #pragma unroll
        for (int i = 0; i < 4; i++) {
            int idx = i * NTHR + tid;
            int o = idx >> 4, c = (idx & 15) * 8;
            cp16((uint32_t)__cvta_generic_to_shared(&Bs[o][c]), Bg + o * D + c);
        }
        asm volatile("cp.async.commit_group;");
        asm volatile("cp.async.wait_group 0;" ::: "memory");
        __syncthreads();                 // tiles ready

        // ---- MMA over this K=128 slab (issued before next gather) ----
        #pragma unroll
        for (int kk = 0; kk < 8; kk++) {
            int kb = kk * 16;
            unsigned a0 = *(unsigned*)&As[rowStrip + gpr    ][kb + tg * 2];
            unsigned a1 = *(unsigned*)&As[rowStrip + gpr + 8][kb + tg * 2];
            unsigned a2 = *(unsigned*)&As[rowStrip + gpr    ][kb + tg * 2 + 8];
            unsigned a3 = *(unsigned*)&As[rowStrip + gpr + 8][kb + tg * 2 + 8];
            #pragma unroll
            for (int t = 0; t < 8; t++) {
                unsigned b0 = *(unsigned*)&Bs[colBase + t * 8 + gpr][kb + tg * 2];
                unsigned b1 = *(unsigned*)&Bs[colBase + t * 8 + gpr][kb + tg * 2 + 8];
                mma_f16(acc[t], a0, a1, a2, a3, b0, b1);
            }
        }

        // ---- gather NEXT slab (relation it) into registers ----
        if (it < 8) {
            int snext = it;
            #pragma unroll 1
            for (int p = 0; p < 4; p++) {
                int node = rowBase + p * 32 + rsub;
                float a[8] = {0.f, 0.f, 0.f, 0.f, 0.f, 0.f, 0.f, 0.f};
                int cnt = 0;
                if (node < n) {
                    int seg = snext * NNODES + node;
                    int e0 = g_off[seg];
                    cnt = g_off[seg + 1] - e0;
                    for (int base = 0; base < cnt; base += 16) {
                        int m = min(16, cnt - base);
                        int idxv = (hl < m) ? __ldg(&g_sorted[e0 + base + hl]) : 0;
                        int j = 0;
                        for (; j + 3 < m; j += 4) {
                            int d0 = __shfl_sync(hmask, idxv, j,     16);
                            int d1 = __shfl_sync(hmask, idxv, j + 1, 16);
                            int d2 = __shfl_sync(hmask, idxv, j + 2, 16);
                            int d3 = __shfl_sync(hmask, idxv, j + 3, 16);
                            uint4 u0 = __ldg((const uint4*)(g_xh + (size_t)d0 * D) + hl);
                            uint4 u1 = __ldg((const uint4*)(g_xh + (size_t)d1 * D) + hl);
                            uint4 u2 = __ldg((const uint4*)(g_xh + (size_t)d2 * D) + hl);
                            uint4 u3 = __ldg((const uint4*)(g_xh + (size_t)d3 * D) + hl);
                            acc_h8(a, u0); acc_h8(a, u1); acc_h8(a, u2); acc_h8(a, u3);
                        }
                        for (; j < m; j++) {
                            int d0 = __shfl_sync(hmask, idxv, j, 16);
                            uint4 u0 = __ldg((const uint4*)(g_xh + (size_t)d0 * D) + hl);
                            acc_h8(a, u0);
                        }
                    }
                }
                float inv = (cnt > 0) ? 1.0f / (float)cnt : 0.0f;
                ((__half2*)&ag[p])[0] = __floats2half2_rn(a[0] * inv, a[1] * inv);
                ((__half2*)&ag[p])[1] = __floats2half2_rn(a[2] * inv, a[3] * inv);
                ((__half2*)&ag[p])[2] = __floats2half2_rn(a[4] * inv, a[5] * inv);
                ((__half2*)&ag[p])[3] = __floats2half2_rn(a[6] * inv, a[7] * inv);
            }
        }
    }

    // ---- epilogue: + bias, store fp32 ----
    #pragma unroll
    for (int t = 0; t < 8; t++) {
        int col = colBase + t * 8 + tg * 2;
        float bv0 = __ldg(bias + col), bv1 = __ldg(bias + col + 1);
        int row0 = rowBase + rowStrip + gpr;
        int row1 = row0 + 8;
        if (row0 < n) {
            float2 v = make_float2(acc[t][0] + bv0, acc[t][1] + bv1);
            *(float2*)(out + (size_t)row0 * D + col) = v;
        }
        if (row1 < n) {
            float2 v = make_float2(acc[t][2] + bv0, acc[t][3] + bv1);
            *(float2*)(out + (size_t)row1 * D + col) = v;
        }
    }
}

extern "C" void kernel_launch(void* const* d_in, const int* in_sizes, int n_in,
                              void* d_out, int out_size) {
    const float* x    = (const float*)d_in[0];
    const int*   ei_w = (const int*)d_in[1];
    const int*   et_w = (const int*)d_in[2];
    const float* W    = (const float*)d_in[3];
    const float* root = (const float*)d_in[4];
    const float* bias = (const float*)d_in[5];
    float*       out  = (float*)d_out;

    int E = in_sizes[1] / 2;
    int n = in_sizes[0] / D;

    static bool attr_set = false;
    if (!attr_set) {
        cudaFuncSetAttribute(k_fused, cudaFuncAttributeMaxDynamicSharedMemorySize, FUSED_SMEM);
        attr_set = true;
    }

    k_prep<<<3200, 512>>>(W, root, x, n, ei_w, et_w);
    k_hist<<<(E + 255) / 256, 256>>>(ei_w, et_w, E);

    {
        const int* a0 = ei_w;
        const int* a1 = et_w;
        int       a2 = E;
        void* args[3] = { (void*)&a0, (void*)&a1, (void*)&a2 };
        cudaLaunchCooperativeKernel((void*)k_css, dim3(148), dim3(1024), args, 0, 0);
    }

    k_fused<<<(n + ROWS - 1) / ROWS, NTHR, FUSED_SMEM>>>(bias, out, n);
}

// round 10
// speedup vs baseline: 1.3641x; 1.3641x over previous
#include <cuda_runtime.h>
#include <cuda_fp16.h>
#include <cooperative_groups.h>
#include <cstdint>

namespace cg = cooperative_groups;

#define NNODES 50000
#define NREL   8
#define D      128
#define NSEG   (NREL * NNODES)      // 400000
#define MAXE   1700000
#define ROWS   128                  // output rows per block
#define NTHR   512

// -------- scratch (device globals; no allocation allowed) --------
__device__ int    g_deg[NSEG];
__device__ int    g_off[NSEG + 1];
__device__ int    g_cur[NSEG];
__device__ int    g_bsum[512];
__device__ int    g_sorted[MAXE];
__device__ int    g_st_ei;
__device__ int    g_st_et;
__device__ __half g_wh[(NREL + 1) * D * D];          // fp16 [W_0..W_7, root], [out][in]
__device__ __half g_xh[(size_t)(NNODES + 128) * D];  // fp16 x (+pad rows)
__device__ __half g_aggh[(size_t)(NSEG + 128) * D];  // fp16 agg (+pad rows)

// -------- merged setup --------
__global__ void k_prep(const float* __restrict__ W, const float* __restrict__ root,
                       const float* __restrict__ x, int n,
                       const int* __restrict__ ei_w, const int* __restrict__ et_w) {
    int i = blockIdx.x * blockDim.x + threadIdx.x;
    int stride = gridDim.x * blockDim.x;
    if (i == 0) {
        bool e64 = true, t64 = true;
        #pragma unroll
        for (int j = 1; j < 64; j += 2) {
            e64 = e64 && (ei_w[j] == 0);
            t64 = t64 && (et_w[j] == 0);
        }
        g_st_ei = e64 ? 2 : 1;
        g_st_et = t64 ? 2 : 1;
    }
    for (int j = i; j < NSEG; j += stride) g_deg[j] = 0;
    const int nw = NREL * D * D;
    for (int j = i; j < nw + D * D; j += stride)
        g_wh[j] = __float2half(j < nw ? W[j] : root[j - nw]);
    int nx4 = n * D / 4;
    for (int j = i; j < nx4; j += stride) {
        float4 v = __ldg((const float4*)x + j);
        __half2* o = (__half2*)(g_xh + (size_t)j * 4);
        o[0] = __floats2half2_rn(v.x, v.y);
        o[1] = __floats2half2_rn(v.z, v.w);
    }
}

__global__ void k_hist(const int* __restrict__ ei_w, const int* __restrict__ et_w, int E) {
    int i = blockIdx.x * blockDim.x + threadIdx.x;
    if (i < E) {
        int st = g_st_ei, stt = g_st_et;
        int s = ei_w[(size_t)i * st];
        int t = et_w[(size_t)i * stt];
        int key = t * NNODES + s;
        if ((unsigned)key < NSEG) atomicAdd(&g_deg[key], 1);
    }
}

// -------- cooperative scan + scatter --------
__global__ void __launch_bounds__(1024)
k_css(const int* __restrict__ ei_w, const int* __restrict__ et_w, int E) {
    __shared__ int sh[1024];
    int tid = threadIdx.x, b = blockIdx.x, nb = gridDim.x;
    int chunk = (NSEG + nb - 1) / nb;
    int lo = b * chunk;
    int hi = min(lo + chunk, NSEG);
    int carry = 0;

    for (int t0 = lo; t0 < hi; t0 += 1024) {
        int i = t0 + tid;
        int v = (i < hi) ? g_deg[i] : 0;
        sh[tid] = v;
        __syncthreads();
        #pragma unroll
        for (int off = 1; off < 1024; off <<= 1) {
            int t = (tid >= off) ? sh[tid - off] : 0;
            __syncthreads();
            sh[tid] += t;
            __syncthreads();
        }
        if (i < hi) g_off[i] = sh[tid] - v + carry;
        int tot = sh[1023];
        __syncthreads();
        carry += tot;
    }
    if (tid == 0) g_bsum[b] = carry;
    cg::this_grid().sync();

    int v2 = (tid < nb) ? g_bsum[tid] : 0;
    sh[tid] = v2;
    __syncthreads();
    #pragma unroll
    for (int off = 1; off < 1024; off <<= 1) {
        int t = (tid >= off) ? sh[tid - off] : 0;
        __syncthreads();
        sh[tid] += t;
        __syncthreads();
    }
    int base = sh[b] - g_bsum[b];
    __syncthreads();
    for (int t0 = lo; t0 < hi; t0 += 1024) {
        int i = t0 + tid;
        if (i < hi) {
            int o = g_off[i] + base;
            g_off[i] = o;
            g_cur[i] = o;
        }
    }
    if (b == 0 && tid == 0) g_off[NSEG] = E;
    cg::this_grid().sync();

    int st = g_st_ei, stt = g_st_et;
    for (int i = b * 1024 + tid; i < E; i += nb * 1024) {
        int s = ei_w[(size_t)i * st];
        int d = ei_w[((size_t)E + i) * st];
        int t = et_w[(size_t)i * stt];
        int key = t * NNODES + s;
        if ((unsigned)key < NSEG) {
            int pos = atomicAdd(&g_cur[key], 1);
            if ((unsigned)pos < MAXE) g_sorted[pos] = d;
        }
    }
}

// -------- gather+mean: half-warp per segment, fp16 out, max occupancy --------
__device__ __forceinline__ void acc_h8(float* a, uint4 u) {
    float2 f0 = __half22float2(*(__half2*)&u.x);
    float2 f1 = __half22float2(*(__half2*)&u.y);
    float2 f2 = __half22float2(*(__half2*)&u.z);
    float2 f3 = __half22float2(*(__half2*)&u.w);
    a[0] += f0.x; a[1] += f0.y; a[2] += f1.x; a[3] += f1.y;
    a[4] += f2.x; a[5] += f2.y; a[6] += f3.x; a[7] += f3.y;
}

__global__ void __launch_bounds__(256)
k_gath() {
    int tid = threadIdx.x;
    int seg = (blockIdx.x * 256 + tid) >> 4;    // half-warp per segment
    int hl  = tid & 15;
    if (seg >= NSEG) return;
    int e0  = g_off[seg];
    int cnt = g_off[seg + 1] - e0;

    float a[8] = {0.f, 0.f, 0.f, 0.f, 0.f, 0.f, 0.f, 0.f};
    int j = 0;
    for (; j + 3 < cnt; j += 4) {
        int d0 = __ldg(&g_sorted[e0 + j]);
        int d1 = __ldg(&g_sorted[e0 + j + 1]);
        int d2 = __ldg(&g_sorted[e0 + j + 2]);
        int d3 = __ldg(&g_sorted[e0 + j + 3]);
        uint4 u0 = __ldg((const uint4*)(g_xh + (size_t)d0 * D) + hl);
        uint4 u1 = __ldg((const uint4*)(g_xh + (size_t)d1 * D) + hl);
        uint4 u2 = __ldg((const uint4*)(g_xh + (size_t)d2 * D) + hl);
        uint4 u3 = __ldg((const uint4*)(g_xh + (size_t)d3 * D) + hl);
        acc_h8(a, u0); acc_h8(a, u1); acc_h8(a, u2); acc_h8(a, u3);
    }
    for (; j < cnt; j++) {
        int d0 = __ldg(&g_sorted[e0 + j]);
        uint4 u0 = __ldg((const uint4*)(g_xh + (size_t)d0 * D) + hl);
        acc_h8(a, u0);
    }
    float inv = (cnt > 0) ? 1.0f / (float)cnt : 0.0f;
    uint4 pk;
    ((__half2*)&pk)[0] = __floats2half2_rn(a[0] * inv, a[1] * inv);
    ((__half2*)&pk)[1] = __floats2half2_rn(a[2] * inv, a[3] * inv);
    ((__half2*)&pk)[2] = __floats2half2_rn(a[4] * inv, a[5] * inv);
    ((__half2*)&pk)[3] = __floats2half2_rn(a[6] * inv, a[7] * inv);
    *((uint4*)(g_aggh + (size_t)seg * D) + hl) = pk;
}

// -------- dense fp16 MMA GEMM over 9 K-slabs --------
__device__ __forceinline__ void mma_f16(float* c,
                                        unsigned a0, unsigned a1, unsigned a2, unsigned a3,
                                        unsigned b0, unsigned b1) {
    asm volatile(
        "mma.sync.aligned.m16n8k16.row.col.f32.f16.f16.f32 "
        "{%0,%1,%2,%3},{%4,%5,%6,%7},{%8,%9},{%0,%1,%2,%3};"
        : "+f"(c[0]), "+f"(c[1]), "+f"(c[2]), "+f"(c[3])
        : "r"(a0), "r"(a1), "r"(a2), "r"(a3), "r"(b0), "r"(b1));
}

__device__ __forceinline__ void cp16(uint32_t sdst, const void* gsrc) {
    asm volatile("cp.async.cg.shared.global [%0], [%1], 16;" :: "r"(sdst), "l"(gsrc));
}

#define GEMM_SMEM (2 * 128 * 136 * 2)   // As + Bs = 69632 B

__global__ void __launch_bounds__(NTHR)
k_gemm(const float* __restrict__ bias, float* __restrict__ out, int n) {
    extern __shared__ __half smh[];
    __half (*As)[136] = (__half(*)[136])smh;
    __half (*Bs)[136] = (__half(*)[136])(smh + 128 * 136);

    int tid  = threadIdx.x;
    int lane = tid & 31;
    int warp = tid >> 5;                 // 0..15
    int rowBase = blockIdx.x * ROWS;
    int gpr = lane >> 2;
    int tg  = lane & 3;
    int rowStrip = (warp & 7) * 16;
    int colBase  = (warp >> 3) * 64;

    float acc[8][4];
    #pragma unroll
    for (int t = 0; t < 8; t++)
        #pragma unroll
        for (int q = 0; q < 4; q++) acc[t][q] = 0.f;

    #pragma unroll 1
    for (int s = 0; s < NREL + 1; s++) {
        __syncthreads();                 // prev MMA done reading tiles

        const __half* Ag = (s < NREL)
            ? (g_aggh + ((size_t)s * NNODES + rowBase) * D)
            : (g_xh + (size_t)rowBase * D);
        const __half* Bg = g_wh + (s << 14);

        #pragma unroll
        for (int i = 0; i < 4; i++) {
            int idx = i * NTHR + tid;
            int r = idx >> 4, c = (idx & 15) * 8;
            cp16((uint32_t)__cvta_generic_to_shared(&As[r][c]), Ag + (size_t)r * D + c);
            cp16((uint32_t)__cvta_generic_to_shared(&Bs[r][c]), Bg + r * D + c);
        }
        asm volatile("cp.async.commit_group;");
        asm volatile("cp.async.wait_group 0;" ::: "memory");
        __syncthreads();

        #pragma unroll
        for (int kk = 0; kk < 8; kk++) {
            int kb = kk * 16;
            unsigned a0 = *(unsigned*)&As[rowStrip + gpr    ][kb + tg * 2];
            unsigned a1 = *(unsigned*)&As[rowStrip + gpr + 8][kb + tg * 2];
            unsigned a2 = *(unsigned*)&As[rowStrip + gpr    ][kb + tg * 2 + 8];
            unsigned a3 = *(unsigned*)&As[rowStrip + gpr + 8][kb + tg * 2 + 8];
            #pragma unroll
            for (int t = 0; t < 8; t++) {
                unsigned b0 = *(unsigned*)&Bs[colBase + t * 8 + gpr][kb + tg * 2];
                unsigned b1 = *(unsigned*)&Bs[colBase + t * 8 + gpr][kb + tg * 2 + 8];
                mma_f16(acc[t], a0, a1, a2, a3, b0, b1);
            }
        }
    }

    #pragma unroll
    for (int t = 0; t < 8; t++) {
        int col = colBase + t * 8 + tg * 2;
        float bv0 = __ldg(bias + col), bv1 = __ldg(bias + col + 1);
        int row0 = rowBase + rowStrip + gpr;
        int row1 = row0 + 8;
        if (row0 < n) {
            float2 v = make_float2(acc[t][0] + bv0, acc[t][1] + bv1);
            *(float2*)(out + (size_t)row0 * D + col) = v;
        }
        if (row1 < n) {
            float2 v = make_float2(acc[t][2] + bv0, acc[t][3] + bv1);
            *(float2*)(out + (size_t)row1 * D + col) = v;
        }
    }
}

extern "C" void kernel_launch(void* const* d_in, const int* in_sizes, int n_in,
                              void* d_out, int out_size) {
    const float* x    = (const float*)d_in[0];
    const int*   ei_w = (const int*)d_in[1];
    const int*   et_w = (const int*)d_in[2];
    const float* W    = (const float*)d_in[3];
    const float* root = (const float*)d_in[4];
    const float* bias = (const float*)d_in[5];
    float*       out  = (float*)d_out;

    int E = in_sizes[1] / 2;
    int n = in_sizes[0] / D;

    static bool attr_set = false;
    if (!attr_set) {
        cudaFuncSetAttribute(k_gemm, cudaFuncAttributeMaxDynamicSharedMemorySize, GEMM_SMEM);
        attr_set = true;
    }

    k_prep<<<3200, 512>>>(W, root, x, n, ei_w, et_w);
    k_hist<<<(E + 255) / 256, 256>>>(ei_w, et_w, E);
    {
        const int* a0 = ei_w;
        const int* a1 = et_w;
        int       a2 = E;
        void* args[3] = { (void*)&a0, (void*)&a1, (void*)&a2 };
        cudaLaunchCooperativeKernel((void*)k_css, dim3(148), dim3(1024), args, 0, 0);
    }
    k_gath<<<(NSEG * 16 + 255) / 256, 256>>>();
    k_gemm<<<(n + ROWS - 1) / ROWS, NTHR, GEMM_SMEM>>>(bias, out, n);
}